// round 3
// baseline (speedup 1.0000x reference)
#include <cuda_runtime.h>
#include <math.h>

// Shapes (fixed by the problem)
#define KS 4
#define KB 8
#define KC 512
#define KL 256
#define KHW 4096
#define KEPS 1e-5f

// Scratch: k, q, v each [4, 8, 256*4096] floats = 128 MB (static __device__, no allocs).
// ctx aliases g_q (safe: attn reads q before writing ctx, 1:1 element ownership,
// and stage-1 regenerates g_q on every graph replay).
__device__ float g_k[(size_t)KS * KB * KL * KHW];
__device__ float g_q[(size_t)KS * KB * KL * KHW];
__device__ float g_v[(size_t)KS * KB * KL * KHW];

struct XPtrs { const float* p[4]; };

// ---------------------------------------------------------------------------
// Stage 1: fused k/q/v projection GEMM + BN/ReLU epilogue.
// Per (s,b): A = W[768x512] (rows 0-255 Wk, 256-511 Wq, 512-767 Wd),
//            B = x[s,b] [512 x 4096], out -> g_k/g_q/g_v in natural [L,HW] layout.
// Tile: 64(M) x 128(N) x 16(K), 256 threads, 4x8 register blocking.
// ---------------------------------------------------------------------------
__global__ __launch_bounds__(256) void proj_kernel(
    XPtrs xp,
    const float* __restrict__ Wk, const float* __restrict__ Wq, const float* __restrict__ Wd,
    const float* __restrict__ bk, const float* __restrict__ bq, const float* __restrict__ bd,
    const float* __restrict__ gk, const float* __restrict__ betak,
    const float* __restrict__ mk, const float* __restrict__ vk,
    const float* __restrict__ gq, const float* __restrict__ betaq,
    const float* __restrict__ mq, const float* __restrict__ vq)
{
    const int tid = threadIdx.x;
    const int s = blockIdx.z >> 3;
    const int b = blockIdx.z & 7;
    const int m0 = blockIdx.y * 64;    // 0..704
    const int n0 = blockIdx.x * 128;   // 0..3968
    const int proj = m0 >> 8;          // 0:k 1:q 2:v
    const int ml0 = m0 & 255;          // row within projection

    const float* W = (proj == 0 ? Wk : (proj == 1 ? Wq : Wd)) + ((size_t)s * KL + ml0) * KC;
    const float* xs = xp.p[s] + (size_t)b * KC * KHW;

    __shared__ float As[16][64];    // [k][m]
    __shared__ float Bs[16][128];   // [k][n]

    const int tm = tid >> 4;           // 0..15
    const int tn = tid & 15;           // 0..15
    const int am = tid >> 2;           // 0..63
    const int ak = (tid & 3) << 2;     // 0,4,8,12
    const int bkr = tid >> 4;          // 0..15
    const int bn0 = (tid & 15) << 3;   // 0..120

    float acc[4][8];
#pragma unroll
    for (int i = 0; i < 4; ++i)
#pragma unroll
        for (int j = 0; j < 8; ++j) acc[i][j] = 0.f;

    for (int k0 = 0; k0 < KC; k0 += 16) {
        float4 a4 = *(const float4*)(W + (size_t)am * KC + k0 + ak);
        As[ak + 0][am] = a4.x;
        As[ak + 1][am] = a4.y;
        As[ak + 2][am] = a4.z;
        As[ak + 3][am] = a4.w;
        const float* bp = xs + (size_t)(k0 + bkr) * KHW + n0 + bn0;
        *(float4*)&Bs[bkr][bn0]     = *(const float4*)(bp);
        *(float4*)&Bs[bkr][bn0 + 4] = *(const float4*)(bp + 4);
        __syncthreads();
#pragma unroll
        for (int kk = 0; kk < 16; ++kk) {
            float4 a  = *(const float4*)&As[kk][tm << 2];
            float4 b0 = *(const float4*)&Bs[kk][tn << 3];
            float4 b1 = *(const float4*)&Bs[kk][(tn << 3) + 4];
            float av[4] = {a.x, a.y, a.z, a.w};
            float bv[8] = {b0.x, b0.y, b0.z, b0.w, b1.x, b1.y, b1.z, b1.w};
#pragma unroll
            for (int i = 0; i < 4; ++i)
#pragma unroll
                for (int j = 0; j < 8; ++j)
                    acc[i][j] = fmaf(av[i], bv[j], acc[i][j]);
        }
        __syncthreads();
    }

    const int sb = (s << 3) | b;
    float* ob = (proj == 0) ? g_k : ((proj == 1) ? g_q : g_v);
#pragma unroll
    for (int i = 0; i < 4; ++i) {
        const int lr = ml0 + (tm << 2) + i;
        const int pi = s * KL + lr;
        float Asc = 1.f, Bsc;
        bool relu = (proj < 2);
        if (proj == 0) {
            float sc = gk[pi] * rsqrtf(vk[pi] + KEPS);
            Asc = sc; Bsc = (bk[pi] - mk[pi]) * sc + betak[pi];
        } else if (proj == 1) {
            float sc = gq[pi] * rsqrtf(vq[pi] + KEPS);
            Asc = sc; Bsc = (bq[pi] - mq[pi]) * sc + betaq[pi];
        } else {
            Bsc = bd[pi];
        }
        float r[8];
#pragma unroll
        for (int j = 0; j < 8; ++j) {
            float t = fmaf(acc[i][j], Asc, Bsc);
            r[j] = relu ? fmaxf(t, 0.f) : t;
        }
        float* op = ob + ((size_t)sb * KL + lr) * KHW + n0 + (tn << 3);
        *(float4*)op       = make_float4(r[0], r[1], r[2], r[3]);
        *(float4*)(op + 4) = make_float4(r[4], r[5], r[6], r[7]);
    }
}

// ---------------------------------------------------------------------------
// Stage 2: scrambled-view 4x4 attention.
// The reference's raw .view means each (b, h', w') attends over a CONTIGUOUS
// 256-element slice of the flattened [L,H,W] block at offset g*256, g=h'*64+w'.
// One block per (b,g): 256 threads, each owns one element l' of the slice.
// ctx output is written in place over g_q.
// ---------------------------------------------------------------------------
__global__ __launch_bounds__(256) void attn_kernel()
{
    const int tid = threadIdx.x;
    const int b = blockIdx.x >> 12;
    const int g = blockIdx.x & 4095;
    const size_t off = (size_t)b * ((size_t)KL * KHW) + (size_t)g * 256 + tid;
    const size_t sstr = (size_t)KB * KL * KHW;  // 8388608

    float qr[4], kr[4], vr[4];
#pragma unroll
    for (int s = 0; s < 4; ++s) {
        qr[s] = g_q[off + s * sstr];
        kr[s] = g_k[off + s * sstr];
        vr[s] = g_v[off + s * sstr];
    }

    // 16 dot products of length 256: per-thread partials + shuffle tree + smem combine
    float p[16];
#pragma unroll
    for (int st = 0; st < 16; ++st) p[st] = qr[st >> 2] * kr[st & 3];
#pragma unroll
    for (int o = 16; o > 0; o >>= 1)
#pragma unroll
        for (int st = 0; st < 16; ++st)
            p[st] += __shfl_xor_sync(0xffffffffu, p[st], o);

    __shared__ float red[16][8];
    __shared__ float attn[16];
    const int wid = tid >> 5, lane = tid & 31;
    if (lane == 0) {
#pragma unroll
        for (int st = 0; st < 16; ++st) red[st][wid] = p[st];
    }
    __syncthreads();
    if (tid < 4) {  // thread tid handles softmax row s=tid
        float sim[4];
#pragma unroll
        for (int t = 0; t < 4; ++t) {
            float v = 0.f;
#pragma unroll
            for (int w = 0; w < 8; ++w) v += red[tid * 4 + t][w];
            sim[t] = v * 0.0625f;  // * L^-0.5 = 1/16
        }
        float mx = fmaxf(fmaxf(sim[0], sim[1]), fmaxf(sim[2], sim[3]));
        float e[4], sum = 0.f;
#pragma unroll
        for (int t = 0; t < 4; ++t) { e[t] = __expf(sim[t] - mx); sum += e[t]; }
        float inv = 1.f / sum;
#pragma unroll
        for (int t = 0; t < 4; ++t) attn[tid * 4 + t] = e[t] * inv;
    }
    __syncthreads();
#pragma unroll
    for (int s = 0; s < 4; ++s) {
        float c = attn[s * 4 + 0] * vr[0] + attn[s * 4 + 1] * vr[1] +
                  attn[s * 4 + 2] * vr[2] + attn[s * 4 + 3] * vr[3];
        g_q[off + s * sstr] = c;   // ctx aliases q (read-before-write, 1:1 ownership)
    }
}

// ---------------------------------------------------------------------------
// Stage 3: up-projection GEMM + residual.
// Per (s,b): out[c,p] = x[c,p] + bu[c] + sum_l Wu[c,l] * ctx[p,l].
// A = Wu[s] [512 x 256] (l contiguous); B^T = ctx[s,b] [4096 x 256] (l contiguous).
// Tile 64(M=c) x 128(N=p) x 16(K=l).  ctx lives in g_q.
// ---------------------------------------------------------------------------
__global__ __launch_bounds__(256) void up_kernel(
    XPtrs xp, const float* __restrict__ Wu, const float* __restrict__ bu,
    float* __restrict__ out)
{
    const int tid = threadIdx.x;
    const int s = blockIdx.z >> 3;
    const int b = blockIdx.z & 7;
    const int m0 = blockIdx.y * 64;    // c
    const int n0 = blockIdx.x * 128;   // p
    const int sb = (s << 3) | b;

    const float* A  = Wu + ((size_t)s * KC + m0) * KL;
    const float* Bt = g_q + (size_t)sb * KL * KHW;     // ctx: [p][l]
    const float* xs = xp.p[s] + (size_t)b * KC * KHW;

    __shared__ float As[16][64];
    __shared__ float Bs[16][128];

    const int tm = tid >> 4;
    const int tn = tid & 15;
    const int am = tid >> 2;           // 0..63
    const int ak = (tid & 3) << 2;     // 0..12
    const int bnr = tid >> 1;          // 0..127 (p within tile)
    const int bkq = (tid & 1) << 3;    // 0 or 8 (l within chunk)

    float acc[4][8];
#pragma unroll
    for (int i = 0; i < 4; ++i)
#pragma unroll
        for (int j = 0; j < 8; ++j) acc[i][j] = 0.f;

    for (int k0 = 0; k0 < KL; k0 += 16) {
        float4 a4 = *(const float4*)(A + (size_t)am * KL + k0 + ak);
        As[ak + 0][am] = a4.x;
        As[ak + 1][am] = a4.y;
        As[ak + 2][am] = a4.z;
        As[ak + 3][am] = a4.w;
        const float* bp = Bt + (size_t)(n0 + bnr) * KL + k0 + bkq;
        float4 b40 = *(const float4*)(bp);
        float4 b41 = *(const float4*)(bp + 4);
        Bs[bkq + 0][bnr] = b40.x; Bs[bkq + 1][bnr] = b40.y;
        Bs[bkq + 2][bnr] = b40.z; Bs[bkq + 3][bnr] = b40.w;
        Bs[bkq + 4][bnr] = b41.x; Bs[bkq + 5][bnr] = b41.y;
        Bs[bkq + 6][bnr] = b41.z; Bs[bkq + 7][bnr] = b41.w;
        __syncthreads();
#pragma unroll
        for (int kk = 0; kk < 16; ++kk) {
            float4 a  = *(const float4*)&As[kk][tm << 2];
            float4 b0 = *(const float4*)&Bs[kk][tn << 3];
            float4 b1 = *(const float4*)&Bs[kk][(tn << 3) + 4];
            float av[4] = {a.x, a.y, a.z, a.w};
            float bv[8] = {b0.x, b0.y, b0.z, b0.w, b1.x, b1.y, b1.z, b1.w};
#pragma unroll
            for (int i = 0; i < 4; ++i)
#pragma unroll
                for (int j = 0; j < 8; ++j)
                    acc[i][j] = fmaf(av[i], bv[j], acc[i][j]);
        }
        __syncthreads();
    }

#pragma unroll
    for (int i = 0; i < 4; ++i) {
        const int c = m0 + (tm << 2) + i;
        const float bias = bu[s * KC + c];
        const float* xrow = xs + (size_t)c * KHW + n0 + (tn << 3);
        float* orow = out + ((size_t)sb * KC + c) * KHW + n0 + (tn << 3);
        float4 x0 = *(const float4*)xrow;
        float4 x1 = *(const float4*)(xrow + 4);
        float xv[8] = {x0.x, x0.y, x0.z, x0.w, x1.x, x1.y, x1.z, x1.w};
        float r[8];
#pragma unroll
        for (int j = 0; j < 8; ++j) r[j] = acc[i][j] + bias + xv[j];
        *(float4*)orow       = make_float4(r[0], r[1], r[2], r[3]);
        *(float4*)(orow + 4) = make_float4(r[4], r[5], r[6], r[7]);
    }
}

// ---------------------------------------------------------------------------
// Launch
// Inputs (metadata order): 0 x_f, 1 x_g, 2 x_h, 3 x_t, 4 Wk, 5 bk, 6 gk,
// 7 betak, 8 mk, 9 vk, 10 Wq, 11 bq, 12 gq, 13 betaq, 14 mq, 15 vq,
// 16 Wd, 17 bd, 18 Wu, 19 bu.  Output: [4,B,C,H,W] fp32.
// ---------------------------------------------------------------------------
extern "C" void kernel_launch(void* const* d_in, const int* in_sizes, int n_in,
                              void* d_out, int out_size)
{
    (void)in_sizes; (void)n_in; (void)out_size;
    XPtrs xp;
    xp.p[0] = (const float*)d_in[0];
    xp.p[1] = (const float*)d_in[1];
    xp.p[2] = (const float*)d_in[2];
    xp.p[3] = (const float*)d_in[3];
    const float* Wk    = (const float*)d_in[4];
    const float* bk    = (const float*)d_in[5];
    const float* gk    = (const float*)d_in[6];
    const float* betak = (const float*)d_in[7];
    const float* mk    = (const float*)d_in[8];
    const float* vk    = (const float*)d_in[9];
    const float* Wq    = (const float*)d_in[10];
    const float* bq    = (const float*)d_in[11];
    const float* gq    = (const float*)d_in[12];
    const float* betaq = (const float*)d_in[13];
    const float* mq    = (const float*)d_in[14];
    const float* vq    = (const float*)d_in[15];
    const float* Wd    = (const float*)d_in[16];
    const float* bd    = (const float*)d_in[17];
    const float* Wu    = (const float*)d_in[18];
    const float* bu    = (const float*)d_in[19];

    dim3 g1(32, 12, 32);   // N tiles (4096/128), M tiles (768/64), s*b
    proj_kernel<<<g1, 256>>>(xp, Wk, Wq, Wd, bk, bq, bd,
                             gk, betak, mk, vk, gq, betaq, mq, vq);

    attn_kernel<<<KB * KHW, 256>>>();

    dim3 g3(32, 8, 32);    // N tiles (4096/128), M tiles (512/64), s*b
    up_kernel<<<g3, 256>>>(xp, Wu, bu, (float*)d_out);
}

// round 6
// speedup vs baseline: 5.9896x; 5.9896x over previous
#include <cuda_runtime.h>
#include <cuda_bf16.h>
#include <cstdint>
#include <math.h>

#define KS 4
#define KB 8
#define KC 512
#define KL 256
#define KHW 4096
#define KEPS 1e-5f

// bf16 scratch (static __device__, no allocs)
__device__ __nv_bfloat16 g_xb[(size_t)KS * KB * KC * KHW];   // x in bf16       134 MB
__device__ __nv_bfloat16 g_w1[(size_t)KS * 768 * KC];        // [Wk;Wq;Wd] bf16   3 MB
__device__ __nv_bfloat16 g_wu[(size_t)KS * KC * KL];         // Wu bf16           1 MB
__device__ __nv_bfloat16 g_kb[(size_t)KS * KB * KL * KHW];   // k scratch        64 MB
__device__ __nv_bfloat16 g_qb[(size_t)KS * KB * KL * KHW];   // q scratch        64 MB
__device__ __nv_bfloat16 g_vb[(size_t)KS * KB * KL * KHW];   // v scratch        64 MB
__device__ __nv_bfloat16 g_ctxb[(size_t)KS * KB * KHW * KL]; // ctx [sb][p][l]   64 MB

struct XPtrs { const float* p[4]; };

// ---------------------------------------------------------------------------
// PTX helpers
// ---------------------------------------------------------------------------
__device__ __forceinline__ unsigned smem_u32(const void* p) {
    return (unsigned)__cvta_generic_to_shared(p);
}
__device__ __forceinline__ void cp16(unsigned s, const void* g) {
    asm volatile("cp.async.cg.shared.global [%0], [%1], 16;" :: "r"(s), "l"(g));
}
__device__ __forceinline__ void cp_commit() {
    asm volatile("cp.async.commit_group;");
}
__device__ __forceinline__ void cp_wait1() {
    asm volatile("cp.async.wait_group 1;");
}
__device__ __forceinline__ void cp_wait0() {
    asm volatile("cp.async.wait_group 0;");
}
__device__ __forceinline__ void ldsm_x4(unsigned& r0, unsigned& r1, unsigned& r2, unsigned& r3, unsigned addr) {
    asm volatile("ldmatrix.sync.aligned.m8n8.x4.shared.b16 {%0,%1,%2,%3},[%4];"
                 : "=r"(r0), "=r"(r1), "=r"(r2), "=r"(r3) : "r"(addr));
}
__device__ __forceinline__ void ldsm_x4_t(unsigned& r0, unsigned& r1, unsigned& r2, unsigned& r3, unsigned addr) {
    asm volatile("ldmatrix.sync.aligned.m8n8.x4.trans.shared.b16 {%0,%1,%2,%3},[%4];"
                 : "=r"(r0), "=r"(r1), "=r"(r2), "=r"(r3) : "r"(addr));
}
__device__ __forceinline__ void mma16816(float* c, const unsigned* a, unsigned b0, unsigned b1) {
    asm volatile("mma.sync.aligned.m16n8k16.row.col.f32.bf16.bf16.f32 "
                 "{%0,%1,%2,%3},{%4,%5,%6,%7},{%8,%9},{%0,%1,%2,%3};"
                 : "+f"(c[0]), "+f"(c[1]), "+f"(c[2]), "+f"(c[3])
                 : "r"(a[0]), "r"(a[1]), "r"(a[2]), "r"(a[3]), "r"(b0), "r"(b1));
}

// ---------------------------------------------------------------------------
// Pre-pass: fp32 -> bf16 conversions
// ---------------------------------------------------------------------------
__global__ __launch_bounds__(256) void convx_kernel(XPtrs xp) {
    size_t i = ((size_t)blockIdx.x * 256 + threadIdx.x) * 8;  // 8 floats/thread
    int s = (int)(i >> 24);                                    // per-stream size = 2^24
    size_t r = i & ((size_t)(1u << 24) - 1);
    const float4* src = (const float4*)(xp.p[s] + r);
    float4 v0 = src[0], v1 = src[1];
    __nv_bfloat162 o[4];
    o[0] = __floats2bfloat162_rn(v0.x, v0.y);
    o[1] = __floats2bfloat162_rn(v0.z, v0.w);
    o[2] = __floats2bfloat162_rn(v1.x, v1.y);
    o[3] = __floats2bfloat162_rn(v1.z, v1.w);
    *(uint4*)(g_xb + i) = *(uint4*)o;
}

__global__ __launch_bounds__(256) void convw_kernel(
    const float* __restrict__ Wk, const float* __restrict__ Wq,
    const float* __restrict__ Wd, const float* __restrict__ Wu)
{
    int idx = blockIdx.x * 256 + threadIdx.x;                  // 2097152 total
    const int W1 = KS * 768 * KC;                              // 1572864
    if (idx < W1) {
        int s = idx / (768 * KC);
        int rem = idx % (768 * KC);
        int row = rem / KC, c = rem % KC;
        const float* src;
        if (row < 256)      src = Wk + ((size_t)s * 256 + row) * KC + c;
        else if (row < 512) src = Wq + ((size_t)s * 256 + (row - 256)) * KC + c;
        else                src = Wd + ((size_t)s * 256 + (row - 512)) * KC + c;
        g_w1[idx] = __float2bfloat16_rn(*src);
    } else {
        int j = idx - W1;                                      // Wu layout identical [4][512][256]
        g_wu[j] = __float2bfloat16_rn(Wu[j]);
    }
}

// ---------------------------------------------------------------------------
// GEMM1 tile loader: A[128x32] from W (K-contig, ld=KC),
// B[32x128] from x (N-contig, ld=KHW).
// ---------------------------------------------------------------------------
__device__ __forceinline__ void g1_load(
    __nv_bfloat16* as, __nv_bfloat16* bs,
    const __nv_bfloat16* Ag, const __nv_bfloat16* Bg, int k0, int tid)
{
    const int c0 = tid * 2, c1 = c0 + 1;
    const int ar0 = c0 >> 2, ac0 = (c0 & 3) << 3;
    const int ar1 = c1 >> 2, ac1 = (c1 & 3) << 3;
    const int br0 = c0 >> 4, bc0 = (c0 & 15) << 3;
    const int br1 = c1 >> 4, bc1 = (c1 & 15) << 3;
    unsigned a_s = smem_u32(as);
    unsigned b_s = smem_u32(bs);
    cp16(a_s + (unsigned)(ar0 * 40 + ac0) * 2u, Ag + (size_t)ar0 * KC + k0 + ac0);
    cp16(a_s + (unsigned)(ar1 * 40 + ac1) * 2u, Ag + (size_t)ar1 * KC + k0 + ac1);
    cp16(b_s + (unsigned)(br0 * 136 + bc0) * 2u, Bg + (size_t)(k0 + br0) * KHW + bc0);
    cp16(b_s + (unsigned)(br1 * 136 + bc1) * 2u, Bg + (size_t)(k0 + br1) * KHW + bc1);
    cp_commit();
}

// ---------------------------------------------------------------------------
// GEMM1: per (s,b) A = [Wk;Wq;Wd] [768x512] bf16 K-contig, B = x_bf16 [512x4096]
// N-contig. 128x128x32 tile, 256 threads, mma m16n8k16, fused BN/ReLU epilogue,
// bf16 outputs into g_kb/g_qb/g_vb.
// ---------------------------------------------------------------------------
__global__ __launch_bounds__(256, 2) void gemm1_kernel(
    const float* __restrict__ bk, const float* __restrict__ gk,
    const float* __restrict__ betak, const float* __restrict__ mk, const float* __restrict__ vk,
    const float* __restrict__ bq, const float* __restrict__ gq,
    const float* __restrict__ betaq, const float* __restrict__ mq, const float* __restrict__ vq,
    const float* __restrict__ bd)
{
    __shared__ __nv_bfloat16 As[2][128 * 40];   // [m][k], row stride 40
    __shared__ __nv_bfloat16 Bs[2][32 * 136];   // [k][n], row stride 136

    const int tid = threadIdx.x;
    const int lane = tid & 31, warp = tid >> 5;
    const int wy = warp >> 1, wx = warp & 1;    // 4 M-warps x 2 N-warps, warp tile 32x64
    const int sb = blockIdx.z;
    const int s = sb >> 3;
    const int m0 = blockIdx.y << 7;
    const int n0 = blockIdx.x << 7;
    const int proj = m0 >> 8;                    // 0:k 1:q 2:v
    const int ml0 = m0 & 255;

    const __nv_bfloat16* Ag = g_w1 + ((size_t)s * 768 + m0) * KC;
    const __nv_bfloat16* Bg = g_xb + (size_t)sb * KC * KHW + n0;

    float acc[2][8][4] = {};

    g1_load(&As[0][0], &Bs[0][0], Ag, Bg, 0, tid);
    int buf = 0;
    for (int kt = 0; kt < 16; ++kt) {
        if (kt < 15) {
            g1_load(&As[buf ^ 1][0], &Bs[buf ^ 1][0], Ag, Bg, (kt + 1) * 32, tid);
            cp_wait1();
        } else {
            cp_wait0();
        }
        __syncthreads();
        unsigned a_base = smem_u32(&As[buf][0]);
        unsigned b_base = smem_u32(&Bs[buf][0]);
#pragma unroll
        for (int ks = 0; ks < 32; ks += 16) {
            unsigned a[2][4];
#pragma unroll
            for (int mi = 0; mi < 2; ++mi) {
                int row = wy * 32 + mi * 16 + (lane & 15);
                int col = ks + ((lane >> 4) << 3);
                ldsm_x4(a[mi][0], a[mi][1], a[mi][2], a[mi][3],
                        a_base + (unsigned)(row * 40 + col) * 2u);
            }
            unsigned bf[4][4];
#pragma unroll
            for (int ni = 0; ni < 4; ++ni) {
                int krow = ks + (lane & 15);
                int ncol = wx * 64 + ni * 16 + ((lane & 16) >> 1);
                ldsm_x4_t(bf[ni][0], bf[ni][1], bf[ni][2], bf[ni][3],
                          b_base + (unsigned)(krow * 136 + ncol) * 2u);
            }
#pragma unroll
            for (int mi = 0; mi < 2; ++mi)
#pragma unroll
                for (int ni = 0; ni < 4; ++ni) {
                    mma16816(acc[mi][ni * 2], a[mi], bf[ni][0], bf[ni][1]);
                    mma16816(acc[mi][ni * 2 + 1], a[mi], bf[ni][2], bf[ni][3]);
                }
        }
        __syncthreads();
        buf ^= 1;
    }

    // Epilogue: BN fold (+ReLU for k,q), write bf16
    __nv_bfloat16* ob = (proj == 0) ? g_kb : ((proj == 1) ? g_qb : g_vb);
#pragma unroll
    for (int mi = 0; mi < 2; ++mi) {
        int rbase = wy * 32 + mi * 16 + (lane >> 2);
#pragma unroll
        for (int h = 0; h < 2; ++h) {
            int Lr = ml0 + rbase + h * 8;
            int pi = s * KL + Lr;
            float Asc, Bsc;
            bool relu = (proj < 2);
            if (proj == 0) {
                float sc = gk[pi] * rsqrtf(vk[pi] + KEPS);
                Asc = sc; Bsc = (bk[pi] - mk[pi]) * sc + betak[pi];
            } else if (proj == 1) {
                float sc = gq[pi] * rsqrtf(vq[pi] + KEPS);
                Asc = sc; Bsc = (bq[pi] - mq[pi]) * sc + betaq[pi];
            } else {
                Asc = 1.f; Bsc = bd[pi];
            }
            __nv_bfloat16* orow = ob + ((size_t)sb * KL + Lr) * KHW + n0 + wx * 64 + (lane & 3) * 2;
#pragma unroll
            for (int ni = 0; ni < 8; ++ni) {
                float v0 = fmaf(acc[mi][ni][h * 2], Asc, Bsc);
                float v1 = fmaf(acc[mi][ni][h * 2 + 1], Asc, Bsc);
                if (relu) { v0 = fmaxf(v0, 0.f); v1 = fmaxf(v1, 0.f); }
                *(__nv_bfloat162*)(orow + ni * 8) = __floats2bfloat162_rn(v0, v1);
            }
        }
    }
}

// ---------------------------------------------------------------------------
// Stage 2: scrambled-view 4x4 attention over contiguous 256-elem slices.
// Reads bf16 k/q/v, writes ctx bf16 in [sb][p][l] layout (l contiguous) so
// stage-3 can ldmatrix it directly.
// ---------------------------------------------------------------------------
__global__ __launch_bounds__(256) void attn_kernel()
{
    const int tid = threadIdx.x;
    const int b = blockIdx.x >> 12;
    const int g = blockIdx.x & 4095;
    const size_t off = (size_t)b * ((size_t)KL * KHW) + (size_t)g * 256 + tid;
    const size_t sstr = (size_t)KB * KL * KHW;

    float qr[4], kr[4], vr[4];
#pragma unroll
    for (int s = 0; s < 4; ++s) {
        qr[s] = __bfloat162float(g_qb[off + s * sstr]);
        kr[s] = __bfloat162float(g_kb[off + s * sstr]);
        vr[s] = __bfloat162float(g_vb[off + s * sstr]);
    }

    float p[16];
#pragma unroll
    for (int st = 0; st < 16; ++st) p[st] = qr[st >> 2] * kr[st & 3];
#pragma unroll
    for (int o = 16; o > 0; o >>= 1)
#pragma unroll
        for (int st = 0; st < 16; ++st)
            p[st] += __shfl_xor_sync(0xffffffffu, p[st], o);

    __shared__ float red[16][8];
    __shared__ float attn[16];
    const int wid = tid >> 5, lane = tid & 31;
    if (lane == 0) {
#pragma unroll
        for (int st = 0; st < 16; ++st) red[st][wid] = p[st];
    }
    __syncthreads();
    if (tid < 4) {
        float sim[4];
#pragma unroll
        for (int t = 0; t < 4; ++t) {
            float v = 0.f;
#pragma unroll
            for (int w = 0; w < 8; ++w) v += red[tid * 4 + t][w];
            sim[t] = v * 0.0625f;
        }
        float mx = fmaxf(fmaxf(sim[0], sim[1]), fmaxf(sim[2], sim[3]));
        float e[4], sum = 0.f;
#pragma unroll
        for (int t = 0; t < 4; ++t) { e[t] = __expf(sim[t] - mx); sum += e[t]; }
        float inv = 1.f / sum;
#pragma unroll
        for (int t = 0; t < 4; ++t) attn[tid * 4 + t] = e[t] * inv;
    }
    __syncthreads();
#pragma unroll
    for (int s = 0; s < 4; ++s) {
        float c = attn[s * 4 + 0] * vr[0] + attn[s * 4 + 1] * vr[1] +
                  attn[s * 4 + 2] * vr[2] + attn[s * 4 + 3] * vr[3];
        g_ctxb[((size_t)(s * KB + b) * KHW + g) * KL + tid] = __float2bfloat16_rn(c);
    }
}

// ---------------------------------------------------------------------------
// GEMM3 tile loader: A[128x32] from Wu (ld=KL), B[128x32] from ctx (ld=KL).
// ---------------------------------------------------------------------------
__device__ __forceinline__ void g3_load(
    __nv_bfloat16* as, __nv_bfloat16* bs,
    const __nv_bfloat16* Ag, const __nv_bfloat16* Bg, int k0, int tid)
{
    const int c0 = tid * 2, c1 = c0 + 1;
    const int r0 = c0 >> 2, o0 = (c0 & 3) << 3;
    const int r1 = c1 >> 2, o1 = (c1 & 3) << 3;
    unsigned a_s = smem_u32(as);
    unsigned b_s = smem_u32(bs);
    cp16(a_s + (unsigned)(r0 * 40 + o0) * 2u, Ag + (size_t)r0 * KL + k0 + o0);
    cp16(a_s + (unsigned)(r1 * 40 + o1) * 2u, Ag + (size_t)r1 * KL + k0 + o1);
    cp16(b_s + (unsigned)(r0 * 40 + o0) * 2u, Bg + (size_t)r0 * KL + k0 + o0);
    cp16(b_s + (unsigned)(r1 * 40 + o1) * 2u, Bg + (size_t)r1 * KL + k0 + o1);
    cp_commit();
}

// ---------------------------------------------------------------------------
// GEMM3: per (s,b) A = Wu [512x256] bf16 K-contig, B = ctx [4096x256] K-contig.
// 128x128x32 tile, non-trans ldmatrix for B fragments, fused bias + residual
// epilogue, fp32 output.
// ---------------------------------------------------------------------------
__global__ __launch_bounds__(256, 2) void gemm3_kernel(
    XPtrs xp, const float* __restrict__ bu, float* __restrict__ out)
{
    __shared__ __nv_bfloat16 As[2][128 * 40];   // [m][k]
    __shared__ __nv_bfloat16 Bs[2][128 * 40];   // [n][k]

    const int tid = threadIdx.x;
    const int lane = tid & 31, warp = tid >> 5;
    const int wy = warp >> 1, wx = warp & 1;
    const int sb = blockIdx.z;
    const int s = sb >> 3, b = sb & 7;
    const int m0 = blockIdx.y << 7;
    const int n0 = blockIdx.x << 7;

    const __nv_bfloat16* Ag = g_wu + ((size_t)s * KC + m0) * KL;
    const __nv_bfloat16* Bg = g_ctxb + ((size_t)sb * KHW + n0) * KL;

    float acc[2][8][4] = {};

    g3_load(&As[0][0], &Bs[0][0], Ag, Bg, 0, tid);
    int buf = 0;
    for (int kt = 0; kt < 8; ++kt) {
        if (kt < 7) {
            g3_load(&As[buf ^ 1][0], &Bs[buf ^ 1][0], Ag, Bg, (kt + 1) * 32, tid);
            cp_wait1();
        } else {
            cp_wait0();
        }
        __syncthreads();
        unsigned a_base = smem_u32(&As[buf][0]);
        unsigned b_base = smem_u32(&Bs[buf][0]);
#pragma unroll
        for (int ks = 0; ks < 32; ks += 16) {
            unsigned a[2][4];
#pragma unroll
            for (int mi = 0; mi < 2; ++mi) {
                int row = wy * 32 + mi * 16 + (lane & 15);
                int col = ks + ((lane >> 4) << 3);
                ldsm_x4(a[mi][0], a[mi][1], a[mi][2], a[mi][3],
                        a_base + (unsigned)(row * 40 + col) * 2u);
            }
            unsigned bf[4][4];
#pragma unroll
            for (int ni = 0; ni < 4; ++ni) {
                int nrow = wx * 64 + ni * 16 + (lane & 7) + ((lane & 16) >> 1);
                int kcol = ks + (lane & 8);
                ldsm_x4(bf[ni][0], bf[ni][1], bf[ni][2], bf[ni][3],
                        b_base + (unsigned)(nrow * 40 + kcol) * 2u);
            }
#pragma unroll
            for (int mi = 0; mi < 2; ++mi)
#pragma unroll
                for (int ni = 0; ni < 4; ++ni) {
                    mma16816(acc[mi][ni * 2], a[mi], bf[ni][0], bf[ni][1]);
                    mma16816(acc[mi][ni * 2 + 1], a[mi], bf[ni][2], bf[ni][3]);
                }
        }
        __syncthreads();
        buf ^= 1;
    }

    // Epilogue: out = x + bu + acc  (fp32)
    const float* xs = xp.p[s] + (size_t)b * KC * KHW;
#pragma unroll
    for (int mi = 0; mi < 2; ++mi) {
        int rbase = wy * 32 + mi * 16 + (lane >> 2);
#pragma unroll
        for (int h = 0; h < 2; ++h) {
            int c = m0 + rbase + h * 8;
            float bias = bu[s * KC + c];
            int pcol = n0 + wx * 64 + (lane & 3) * 2;
            const float* xrow = xs + (size_t)c * KHW + pcol;
            float* orow = out + ((size_t)sb * KC + c) * KHW + pcol;
#pragma unroll
            for (int ni = 0; ni < 8; ++ni) {
                float2 xv = *(const float2*)(xrow + ni * 8);
                float2 r;
                r.x = acc[mi][ni][h * 2] + bias + xv.x;
                r.y = acc[mi][ni][h * 2 + 1] + bias + xv.y;
                *(float2*)(orow + ni * 8) = r;
            }
        }
    }
}

// ---------------------------------------------------------------------------
// Launch. Inputs: 0-3 x_f..x_t, 4 Wk, 5 bk, 6 gk, 7 betak, 8 mk, 9 vk,
// 10 Wq, 11 bq, 12 gq, 13 betaq, 14 mq, 15 vq, 16 Wd, 17 bd, 18 Wu, 19 bu.
// ---------------------------------------------------------------------------
extern "C" void kernel_launch(void* const* d_in, const int* in_sizes, int n_in,
                              void* d_out, int out_size)
{
    (void)in_sizes; (void)n_in; (void)out_size;
    XPtrs xp;
    xp.p[0] = (const float*)d_in[0];
    xp.p[1] = (const float*)d_in[1];
    xp.p[2] = (const float*)d_in[2];
    xp.p[3] = (const float*)d_in[3];
    const float* Wk    = (const float*)d_in[4];
    const float* bk    = (const float*)d_in[5];
    const float* gk    = (const float*)d_in[6];
    const float* betak = (const float*)d_in[7];
    const float* mk    = (const float*)d_in[8];
    const float* vk    = (const float*)d_in[9];
    const float* Wq    = (const float*)d_in[10];
    const float* bq    = (const float*)d_in[11];
    const float* gq    = (const float*)d_in[12];
    const float* betaq = (const float*)d_in[13];
    const float* mq    = (const float*)d_in[14];
    const float* vq    = (const float*)d_in[15];
    const float* Wd    = (const float*)d_in[16];
    const float* bd    = (const float*)d_in[17];
    const float* Wu    = (const float*)d_in[18];
    const float* bu    = (const float*)d_in[19];

    convw_kernel<<<8192, 256>>>(Wk, Wq, Wd, Wu);
    convx_kernel<<<32768, 256>>>(xp);

    dim3 g1(32, 6, 32);   // N tiles, M tiles (768/128), s*b
    gemm1_kernel<<<g1, 256>>>(bk, gk, betak, mk, vk, bq, gq, betaq, mq, vq, bd);

    attn_kernel<<<KB * KHW, 256>>>();

    dim3 g3(32, 4, 32);   // N tiles, M tiles (512/128), s*b
    gemm3_kernel<<<g3, 256>>>(xp, bu, (float*)d_out);
}